// round 2
// baseline (speedup 1.0000x reference)
#include <cuda_runtime.h>
#include <math.h>

#define VOCAB   1000000
#define DIM     128
#define BATCH   4096
#define NEG     5
#define LMAX    4
#define NROWS   40960            // BATCH * 2 * WINDOW

__device__ __forceinline__ float log_sigmoid(float x) {
    return fminf(x, 0.0f) - log1pf(__expf(-fabsf(x)));
}

__device__ __forceinline__ void add4(float4& a, const float4 b) {
    a.x += b.x; a.y += b.y; a.z += b.z; a.w += b.w;
}

__device__ __forceinline__ float dot4(const float4 a, const float4 b) {
    return a.x * b.x + a.y * b.y + a.z * b.z + a.w * b.w;
}

__device__ __forceinline__ float warp_sum(float v) {
    #pragma unroll
    for (int off = 16; off > 0; off >>= 1)
        v += __shfl_xor_sync(0xFFFFFFFFu, v, off);
    return v;
}

__device__ __forceinline__ float4 grow(const float* __restrict__ t, int i, int col) {
    return __ldg(reinterpret_cast<const float4*>(t + (size_t)i * DIM + col));
}

// Gather one ragged bag (len in [1,LMAX]) with fully predicated, mutually
// independent 512B row loads. No reductions inside — keeps MLP maximal.
__device__ __forceinline__ void bag_gather(float4& acc, const float* __restrict__ t,
                                           const int4 i4, const int len, const int col) {
    add4(acc, grow(t, i4.x, col));                 // len >= 1 always
    if (len > 1) add4(acc, grow(t, i4.y, col));
    if (len > 2) add4(acc, grow(t, i4.z, col));
    if (len > 3) add4(acc, grow(t, i4.w, col));
}

__global__ void zero_out_kernel(float* out) { out[0] = 0.0f; }

__global__ void __launch_bounds__(128)
skipgram_kernel(const float* __restrict__ u_table,
                const float* __restrict__ v_table,
                const int*   __restrict__ pos_u_idx,
                const int*   __restrict__ pos_u_len,
                const int*   __restrict__ pos_v_idx,
                const int*   __restrict__ pos_v_len,
                const int*   __restrict__ neg_v_idx,
                const int*   __restrict__ neg_v_len,
                float* __restrict__ out) {
    const int row   = blockIdx.x * 4 + (threadIdx.x >> 5);  // one warp per output row
    const int lane  = threadIdx.x & 31;
    const int col   = lane * 4;
    const int wslot = threadIdx.x >> 5;

    __shared__ float s_partial[4];

    // ---- all metadata up front (int4 index quads, broadcast across warp) ----
    const int4 ui = __ldg(reinterpret_cast<const int4*>(pos_u_idx) + row);
    const int4 vi = __ldg(reinterpret_cast<const int4*>(pos_v_idx) + row);
    const int4 n0 = __ldg(reinterpret_cast<const int4*>(neg_v_idx) + (size_t)row * NEG + 0);
    const int4 n1 = __ldg(reinterpret_cast<const int4*>(neg_v_idx) + (size_t)row * NEG + 1);
    const int4 n2 = __ldg(reinterpret_cast<const int4*>(neg_v_idx) + (size_t)row * NEG + 2);
    const int4 n3 = __ldg(reinterpret_cast<const int4*>(neg_v_idx) + (size_t)row * NEG + 3);
    const int4 n4 = __ldg(reinterpret_cast<const int4*>(neg_v_idx) + (size_t)row * NEG + 4);
    const int ulen  = __ldg(pos_u_len + row);
    const int vlen  = __ldg(pos_v_len + row);
    const int l0 = __ldg(neg_v_len + (size_t)row * NEG + 0);
    const int l1 = __ldg(neg_v_len + (size_t)row * NEG + 1);
    const int l2 = __ldg(neg_v_len + (size_t)row * NEG + 2);
    const int l3 = __ldg(neg_v_len + (size_t)row * NEG + 3);
    const int l4 = __ldg(neg_v_len + (size_t)row * NEG + 4);

    // ---- 28 independent row gathers: 7 bags, separate accumulators ----
    float4 au = make_float4(0.f,0.f,0.f,0.f);
    float4 av = make_float4(0.f,0.f,0.f,0.f);
    float4 a0 = make_float4(0.f,0.f,0.f,0.f);
    float4 a1 = make_float4(0.f,0.f,0.f,0.f);
    float4 a2 = make_float4(0.f,0.f,0.f,0.f);
    float4 a3 = make_float4(0.f,0.f,0.f,0.f);
    float4 a4 = make_float4(0.f,0.f,0.f,0.f);

    bag_gather(au, u_table, ui, ulen, col);
    bag_gather(av, v_table, vi, vlen, col);
    bag_gather(a0, v_table, n0, l0, col);
    bag_gather(a1, v_table, n1, l1, col);
    bag_gather(a2, v_table, n2, l2, col);
    bag_gather(a3, v_table, n3, l3, col);
    bag_gather(a4, v_table, n4, l4, col);

    // ---- epilogue: dots, reductions, log-sigmoids ----
    const float inv_u = 1.0f / (float)ulen;
    float4 eu;
    eu.x = au.x * inv_u; eu.y = au.y * inv_u; eu.z = au.z * inv_u; eu.w = au.w * inv_u;

    float sp = warp_sum(dot4(eu, av)) / (float)vlen;
    float s0 = warp_sum(dot4(eu, a0)) / (float)l0;
    float s1 = warp_sum(dot4(eu, a1)) / (float)l1;
    float s2 = warp_sum(dot4(eu, a2)) / (float)l2;
    float s3 = warp_sum(dot4(eu, a3)) / (float)l3;
    float s4 = warp_sum(dot4(eu, a4)) / (float)l4;

    float loss = log_sigmoid(sp)
               + log_sigmoid(-s0) + log_sigmoid(-s1) + log_sigmoid(-s2)
               + log_sigmoid(-s3) + log_sigmoid(-s4);

    if (lane == 0) s_partial[wslot] = -loss * (1.0f / (float)BATCH);
    __syncthreads();

    if (threadIdx.x == 0) {
        float bsum = s_partial[0] + s_partial[1] + s_partial[2] + s_partial[3];
        atomicAdd(out, bsum);
    }
}

extern "C" void kernel_launch(void* const* d_in, const int* in_sizes, int n_in,
                              void* d_out, int out_size) {
    const float* u_table   = (const float*)d_in[0];
    const float* v_table   = (const float*)d_in[1];
    const int*   pos_u_idx = (const int*)d_in[2];
    const int*   pos_u_len = (const int*)d_in[3];
    const int*   pos_v_idx = (const int*)d_in[4];
    const int*   pos_v_len = (const int*)d_in[5];
    const int*   neg_v_idx = (const int*)d_in[6];
    const int*   neg_v_len = (const int*)d_in[7];
    float* out = (float*)d_out;

    zero_out_kernel<<<1, 1>>>(out);
    skipgram_kernel<<<NROWS / 4, 128>>>(u_table, v_table,
                                        pos_u_idx, pos_u_len,
                                        pos_v_idx, pos_v_len,
                                        neg_v_idx, neg_v_len, out);
}

// round 3
// speedup vs baseline: 1.1324x; 1.1324x over previous
#include <cuda_runtime.h>
#include <math.h>

#define VOCAB   1000000
#define DIM     128
#define BATCH   4096
#define NEG     5
#define LMAX    4
#define NROWS   40960            // BATCH * 2 * WINDOW

__device__ __forceinline__ float log_sigmoid(float x) {
    return fminf(x, 0.0f) - log1pf(__expf(-fabsf(x)));
}

__device__ __forceinline__ void add4(float4& a, const float4 b) {
    a.x += b.x; a.y += b.y; a.z += b.z; a.w += b.w;
}

__device__ __forceinline__ float dot4(const float4 a, const float4 b) {
    return a.x * b.x + a.y * b.y + a.z * b.z + a.w * b.w;
}

__device__ __forceinline__ float4 grow(const float* __restrict__ t, int i, int col) {
    return __ldg(reinterpret_cast<const float4*>(t + (size_t)i * DIM + col));
}

// Ragged bag gather: up to 4 independent 512B row loads, predicated on len.
__device__ __forceinline__ void bag_gather(float4& acc, const float* __restrict__ t,
                                           const int4 i4, const int len, const int col) {
    add4(acc, grow(t, i4.x, col));                 // len >= 1 always
    if (len > 1) add4(acc, grow(t, i4.y, col));
    if (len > 2) add4(acc, grow(t, i4.z, col));
    if (len > 3) add4(acc, grow(t, i4.w, col));
}

__global__ void zero_out_kernel(float* out) { out[0] = 0.0f; }

__global__ void __launch_bounds__(256, 6)
skipgram_kernel(const float* __restrict__ u_table,
                const float* __restrict__ v_table,
                const int*   __restrict__ pos_u_idx,
                const int*   __restrict__ pos_u_len,
                const int*   __restrict__ pos_v_idx,
                const int*   __restrict__ pos_v_len,
                const int*   __restrict__ neg_v_idx,
                const int*   __restrict__ neg_v_len,
                float* __restrict__ out) {
    const int row   = blockIdx.x * 8 + (threadIdx.x >> 5);  // one warp per row
    const int lane  = threadIdx.x & 31;
    const int col   = lane * 4;
    const int wslot = threadIdx.x >> 5;

    __shared__ float s_partial[8];

    // ---- positive bags: u and v, 8 independent gathers ----
    const int  ulen = __ldg(pos_u_len + row);
    const int  vlen = __ldg(pos_v_len + row);
    const int4 ui   = __ldg(reinterpret_cast<const int4*>(pos_u_idx) + row);
    const int4 vi   = __ldg(reinterpret_cast<const int4*>(pos_v_idx) + row);

    float4 au = make_float4(0.f,0.f,0.f,0.f);
    float4 av = make_float4(0.f,0.f,0.f,0.f);
    bag_gather(au, u_table, ui, ulen, col);
    bag_gather(av, v_table, vi, vlen, col);

    // prefetch negative bag 0 metadata while positive gathers are in flight
    const int4* nip = reinterpret_cast<const int4*>(neg_v_idx) + (size_t)row * NEG;
    const int*  nlp = neg_v_len + (size_t)row * NEG;
    int4 nq = __ldg(nip);
    int  nl = __ldg(nlp);

    const float inv_u = 1.0f / (float)ulen;
    float4 eu;
    eu.x = au.x * inv_u; eu.y = au.y * inv_u; eu.z = au.z * inv_u; eu.w = au.w * inv_u;

    // per-lane partial of positive score (divide by len per-lane: linear op)
    float dpos = dot4(eu, av) / (float)vlen;

    // ---- negatives: pipeline idx prefetch one bag ahead ----
    float d[NEG];
    #pragma unroll
    for (int k = 0; k < NEG; ++k) {
        const int4 cq = nq;
        const int  cl = nl;
        if (k + 1 < NEG) {            // prefetch next bag's metadata
            nq = __ldg(nip + k + 1);
            nl = __ldg(nlp + k + 1);
        }
        float4 a = make_float4(0.f,0.f,0.f,0.f);
        bag_gather(a, v_table, cq, cl, col);
        d[k] = dot4(eu, a) / (float)cl;   // per-lane partial, no reduction yet
    }

    // ---- batched reductions: 6 independent shuffle trees, pipelined ----
    #pragma unroll
    for (int off = 16; off > 0; off >>= 1) {
        dpos += __shfl_xor_sync(0xFFFFFFFFu, dpos, off);
        #pragma unroll
        for (int k = 0; k < NEG; ++k)
            d[k] += __shfl_xor_sync(0xFFFFFFFFu, d[k], off);
    }

    float loss = log_sigmoid(dpos);
    #pragma unroll
    for (int k = 0; k < NEG; ++k)
        loss += log_sigmoid(-d[k]);

    if (lane == 0) s_partial[wslot] = -loss * (1.0f / (float)BATCH);
    __syncthreads();

    if (threadIdx.x == 0) {
        float bsum = 0.f;
        #pragma unroll
        for (int i = 0; i < 8; ++i) bsum += s_partial[i];
        atomicAdd(out, bsum);
    }
}

extern "C" void kernel_launch(void* const* d_in, const int* in_sizes, int n_in,
                              void* d_out, int out_size) {
    const float* u_table   = (const float*)d_in[0];
    const float* v_table   = (const float*)d_in[1];
    const int*   pos_u_idx = (const int*)d_in[2];
    const int*   pos_u_len = (const int*)d_in[3];
    const int*   pos_v_idx = (const int*)d_in[4];
    const int*   pos_v_len = (const int*)d_in[5];
    const int*   neg_v_idx = (const int*)d_in[6];
    const int*   neg_v_len = (const int*)d_in[7];
    float* out = (float*)d_out;

    zero_out_kernel<<<1, 1>>>(out);
    skipgram_kernel<<<NROWS / 8, 256>>>(u_table, v_table,
                                        pos_u_idx, pos_u_len,
                                        pos_v_idx, pos_v_len,
                                        neg_v_idx, neg_v_len, out);
}

// round 4
// speedup vs baseline: 1.2323x; 1.0882x over previous
#include <cuda_runtime.h>
#include <math.h>

#define VOCAB   1000000
#define DIM     128
#define BATCH   4096
#define NEG     5
#define LMAX    4
#define NROWS   40960            // BATCH * 2 * WINDOW
#define WPB     8                // warps per block

__device__ __forceinline__ float log_sigmoid(float x) {
    return fminf(x, 0.0f) - log1pf(__expf(-fabsf(x)));
}

__device__ __forceinline__ void add4(float4& a, const float4 b) {
    a.x += b.x; a.y += b.y; a.z += b.z; a.w += b.w;
}

__device__ __forceinline__ float dot4(const float4 a, const float4 b) {
    return a.x * b.x + a.y * b.y + a.z * b.z + a.w * b.w;
}

__device__ __forceinline__ float warp_sum(float v) {
    #pragma unroll
    for (int off = 16; off > 0; off >>= 1)
        v += __shfl_xor_sync(0xFFFFFFFFu, v, off);
    return v;
}

__device__ __forceinline__ float4 grow(const float* __restrict__ t, int i, int col) {
    return __ldg(reinterpret_cast<const float4*>(t + (size_t)i * DIM + col));
}

// Ragged bag gather: up to 4 independent predicated 512B row loads.
__device__ __forceinline__ float4 bag_gather(const float* __restrict__ t,
                                             const int4 i4, const int len, const int col) {
    float4 acc = grow(t, i4.x, col);               // len >= 1 always
    if (len > 1) add4(acc, grow(t, i4.y, col));
    if (len > 2) add4(acc, grow(t, i4.z, col));
    if (len > 3) add4(acc, grow(t, i4.w, col));
    return acc;
}

__global__ void zero_out_kernel(float* out) { out[0] = 0.0f; }

__global__ void __launch_bounds__(256)
skipgram_kernel(const float* __restrict__ u_table,
                const float* __restrict__ v_table,
                const int*   __restrict__ pos_u_idx,
                const int*   __restrict__ pos_u_len,
                const int*   __restrict__ pos_v_idx,
                const int*   __restrict__ pos_v_len,
                const int*   __restrict__ neg_v_idx,
                const int*   __restrict__ neg_v_len,
                float* __restrict__ out) {
    const int wslot = threadIdx.x >> 5;
    const int row   = blockIdx.x * WPB + wslot;    // one warp per output row
    const int lane  = threadIdx.x & 31;
    const int col   = lane * 4;

    // Per-warp metadata staging: 28 index ints (bags: u, v, n0..n4) + 7 lens.
    // 112B idx stride keeps [wslot][bag*4] 16B-aligned for LDS.128.
    __shared__ __align__(16) int s_idx[WPB][28];
    __shared__ int   s_len[WPB][8];
    __shared__ float s_partial[WPB];

    // lane-parallel metadata load (warp-local; one LDG per lane + 7-lane len load)
    if (lane < 4)        s_idx[wslot][lane] = __ldg(pos_u_idx + row * 4 + lane);
    else if (lane < 8)   s_idx[wslot][lane] = __ldg(pos_v_idx + row * 4 + (lane - 4));
    else if (lane < 28)  s_idx[wslot][lane] = __ldg(neg_v_idx + (size_t)row * 20 + (lane - 8));
    if (lane < 7) {
        const int* p = (lane == 0) ? pos_u_len + row
                     : (lane == 1) ? pos_v_len + row
                     :               neg_v_len + (size_t)row * NEG + (lane - 2);
        s_len[wslot][lane] = __ldg(p);
    }
    __syncwarp();

    // ---- positive bags (8 independent row gathers in flight) ----
    const int4 ui = *reinterpret_cast<const int4*>(&s_idx[wslot][0]);
    const int4 vi = *reinterpret_cast<const int4*>(&s_idx[wslot][4]);
    const int ulen = s_len[wslot][0];
    const int vlen = s_len[wslot][1];

    float4 au = bag_gather(u_table, ui, ulen, col);
    float4 av = bag_gather(v_table, vi, vlen, col);

    const float inv_u = 1.0f / (float)ulen;
    float4 eu;
    eu.x = au.x * inv_u; eu.y = au.y * inv_u; eu.z = au.z * inv_u; eu.w = au.w * inv_u;

    float score = warp_sum(dot4(eu, av)) / (float)vlen;
    float loss  = log_sigmoid(score);

    // ---- negatives: idx quad comes from smem (29cyc) not gmem (234+cyc) ----
    #pragma unroll
    for (int k = 0; k < NEG; ++k) {
        const int4 nq = *reinterpret_cast<const int4*>(&s_idx[wslot][8 + k * 4]);
        const int  nl = s_len[wslot][2 + k];
        float4 a = bag_gather(v_table, nq, nl, col);
        float ns = warp_sum(dot4(eu, a)) / (float)nl;
        loss += log_sigmoid(-ns);
    }

    if (lane == 0) s_partial[wslot] = -loss * (1.0f / (float)BATCH);
    __syncthreads();

    if (threadIdx.x == 0) {
        float bsum = 0.f;
        #pragma unroll
        for (int i = 0; i < WPB; ++i) bsum += s_partial[i];
        atomicAdd(out, bsum);
    }
}

extern "C" void kernel_launch(void* const* d_in, const int* in_sizes, int n_in,
                              void* d_out, int out_size) {
    const float* u_table   = (const float*)d_in[0];
    const float* v_table   = (const float*)d_in[1];
    const int*   pos_u_idx = (const int*)d_in[2];
    const int*   pos_u_len = (const int*)d_in[3];
    const int*   pos_v_idx = (const int*)d_in[4];
    const int*   pos_v_len = (const int*)d_in[5];
    const int*   neg_v_idx = (const int*)d_in[6];
    const int*   neg_v_len = (const int*)d_in[7];
    float* out = (float*)d_out;

    zero_out_kernel<<<1, 1>>>(out);
    skipgram_kernel<<<NROWS / WPB, 256>>>(u_table, v_table,
                                          pos_u_idx, pos_u_len,
                                          pos_v_idx, pos_v_len,
                                          neg_v_idx, neg_v_len, out);
}